// round 8
// baseline (speedup 1.0000x reference)
#include <cuda_runtime.h>

// PointAttentionEncoder1D — 2 threads/point (16 ch each), f32x2 packed,
// neighbor-PAIR processing so every weight LDS feeds FMAs for two neighbors.

typedef unsigned long long u64;
constexpr int KNB = 16;

__device__ __forceinline__ u64 pack2(float lo, float hi) {
    u64 r; asm("mov.b64 %0, {%1,%2};" : "=l"(r) : "f"(lo), "f"(hi)); return r;
}
__device__ __forceinline__ void unpack2(u64 v, float& lo, float& hi) {
    asm("mov.b64 {%0,%1}, %2;" : "=f"(lo), "=f"(hi) : "l"(v));
}
__device__ __forceinline__ u64 fma2(u64 a, u64 b, u64 c) {
    u64 d; asm("fma.rn.f32x2 %0, %1, %2, %3;" : "=l"(d) : "l"(a), "l"(b), "l"(c)); return d;
}
__device__ __forceinline__ u64 add2(u64 a, u64 b) {
    u64 d; asm("add.rn.f32x2 %0, %1, %2;" : "=l"(d) : "l"(a), "l"(b)); return d;
}
__device__ __forceinline__ u64 neg2(u64 a) { return a ^ 0x8000000080000000ULL; }
__device__ __forceinline__ float leaky(float v) { return fmaxf(v, 0.01f * v); }

// ---- single: MLP 3->16(leaky)->32, this thread's 16-channel half ----
__device__ __forceinline__ void mlp_half(
    const float* __restrict__ w1, const float* __restrict__ b1,
    const float* __restrict__ w2h, const float* __restrict__ b2h,
    float x0, float x1, float x2, u64* __restrict__ o)
{
    const u64 X0 = pack2(x0, x0), X1 = pack2(x1, x1), X2 = pack2(x2, x2);
    float h[16];
#pragma unroll
    for (int i = 0; i < 8; i++) {
        u64 a = *(const u64*)(b1 + 2 * i);
        a = fma2(X0, *(const u64*)(w1 + 2 * i),      a);
        a = fma2(X1, *(const u64*)(w1 + 16 + 2 * i), a);
        a = fma2(X2, *(const u64*)(w1 + 32 + 2 * i), a);
        float va, vb; unpack2(a, va, vb);
        h[2 * i] = leaky(va); h[2 * i + 1] = leaky(vb);
    }
    const ulonglong2* bb = (const ulonglong2*)b2h;
#pragma unroll
    for (int c = 0; c < 4; c++) { ulonglong2 t = bb[c]; o[2*c] = t.x; o[2*c+1] = t.y; }
#pragma unroll
    for (int i = 0; i < 16; i++) {
        const u64 h2 = pack2(h[i], h[i]);
        const ulonglong2* w2r = (const ulonglong2*)(w2h + i * 32);
#pragma unroll
        for (int c = 0; c < 4; c++) {
            ulonglong2 t = w2r[c];
            o[2*c]   = fma2(h2, t.x, o[2*c]);
            o[2*c+1] = fma2(h2, t.y, o[2*c+1]);
        }
    }
}

// ---- dual: same MLP evaluated for two inputs, weight loads shared ----
__device__ __forceinline__ void mlp_half_dual(
    const float* __restrict__ w1, const float* __restrict__ b1,
    const float* __restrict__ w2h, const float* __restrict__ b2h,
    float a0, float a1, float a2, float e0, float e1, float e2,
    u64* __restrict__ oa, u64* __restrict__ ob)
{
    const u64 A0 = pack2(a0, a0), A1 = pack2(a1, a1), A2 = pack2(a2, a2);
    const u64 B0 = pack2(e0, e0), B1 = pack2(e1, e1), B2 = pack2(e2, e2);
    float ha[16], hb[16];
#pragma unroll
    for (int i = 0; i < 8; i++) {
        u64 w0  = *(const u64*)(w1 + 2 * i);
        u64 w16 = *(const u64*)(w1 + 16 + 2 * i);
        u64 w32 = *(const u64*)(w1 + 32 + 2 * i);
        u64 bb  = *(const u64*)(b1 + 2 * i);
        u64 sa = fma2(A0, w0, bb); sa = fma2(A1, w16, sa); sa = fma2(A2, w32, sa);
        u64 sb = fma2(B0, w0, bb); sb = fma2(B1, w16, sb); sb = fma2(B2, w32, sb);
        float va, vb; unpack2(sa, va, vb);
        ha[2*i] = leaky(va); ha[2*i+1] = leaky(vb);
        unpack2(sb, va, vb);
        hb[2*i] = leaky(va); hb[2*i+1] = leaky(vb);
    }
    const ulonglong2* bbv = (const ulonglong2*)b2h;
#pragma unroll
    for (int c = 0; c < 4; c++) {
        ulonglong2 t = bbv[c];
        oa[2*c] = t.x; oa[2*c+1] = t.y;
        ob[2*c] = t.x; ob[2*c+1] = t.y;
    }
#pragma unroll
    for (int i = 0; i < 16; i++) {
        const u64 h2a = pack2(ha[i], ha[i]);
        const u64 h2b = pack2(hb[i], hb[i]);
        const ulonglong2* w2r = (const ulonglong2*)(w2h + i * 32);
#pragma unroll
        for (int c = 0; c < 4; c++) {
            ulonglong2 t = w2r[c];
            oa[2*c]   = fma2(h2a, t.x, oa[2*c]);
            oa[2*c+1] = fma2(h2a, t.y, oa[2*c+1]);
            ob[2*c]   = fma2(h2b, t.x, ob[2*c]);
            ob[2*c+1] = fma2(h2b, t.y, ob[2*c+1]);
        }
    }
}

__global__ void __launch_bounds__(128, 3)
pae_kernel(const float* __restrict__ center,   // [P,1,3]
           const float* __restrict__ other,    // [P,K,3]
           const float* __restrict__ mw1,      // [6,3,16]
           const float* __restrict__ mb1,      // [6,16]
           const float* __restrict__ mw2,      // [6,16,32]
           const float* __restrict__ mb2,      // [6,32]
           const float* __restrict__ ww1,      // [32,64]
           const float* __restrict__ wb1,      // [64]
           const float* __restrict__ ww2,      // [64,32]
           const float* __restrict__ wb2,      // [32]
           float* __restrict__ out,            // [P,32]
           int P)
{
    __shared__ __align__(16) float s_mw1[6 * 48];
    __shared__ __align__(16) float s_mb1[6 * 16];
    __shared__ __align__(16) float s_mw2[6 * 512];
    __shared__ __align__(16) float s_mb2[6 * 32];
    __shared__ __align__(16) float s_w1t[64 * 32];   // wp_w1 transposed: [m][c]
    __shared__ __align__(16) float s_wb1[64];
    __shared__ __align__(16) float s_w2[64 * 32];    // wp_w2: [m][c]
    __shared__ __align__(16) float s_wb2[32];

    const int tid = threadIdx.x;
    const int nt  = blockDim.x;
    for (int i = tid; i < 6 * 48;  i += nt) s_mw1[i] = mw1[i];
    for (int i = tid; i < 6 * 16;  i += nt) s_mb1[i] = mb1[i];
    for (int i = tid; i < 6 * 512; i += nt) s_mw2[i] = mw2[i];
    for (int i = tid; i < 6 * 32;  i += nt) s_mb2[i] = mb2[i];
    for (int i = tid; i < 32 * 64; i += nt) {
        int c = i >> 6, m = i & 63;
        s_w1t[m * 32 + c] = ww1[i];
    }
    for (int i = tid; i < 64;      i += nt) s_wb1[i] = wb1[i];
    for (int i = tid; i < 64 * 32; i += nt) s_w2[i] = ww2[i];
    for (int i = tid; i < 32;      i += nt) s_wb2[i] = wb2[i];
    __syncthreads();

    const int g = blockIdx.x * nt + tid;
    if (g >= 2 * P) return;
    const int p    = g >> 1;
    const int half = g & 1;
    const int co   = 16 * half;

    const float cx = center[p * 3 + 0];
    const float cy = center[p * 3 + 1];
    const float cz = center[p * 3 + 2];

    u64 q2[8];
    mlp_half(s_mw1, s_mb1, s_mw2 + co, s_mb2 + co, cx, cy, cz, q2);

    u64 acc2[8];
#pragma unroll
    for (int c = 0; c < 8; c++) acc2[c] = 0ULL;

    // ================= j = 0 : center-as-neighbor (single path) =================
    {
        u64 pos2[8];
        mlp_half(s_mw1 + 5*48, s_mb1 + 5*16, s_mw2 + 5*512 + co, s_mb2 + 5*32 + co,
                 0.f, 0.f, 0.f, pos2);
        u64 u2[8];
        mlp_half(s_mw1 + 1*48, s_mb1 + 1*16, s_mw2 + 1*512 + co, s_mb2 + 1*32 + co,
                 cx, cy, cz, u2);
#pragma unroll
        for (int c = 0; c < 8; c++)
            u2[c] = add2(add2(q2[c], pos2[c]), neg2(u2[c]));

        u64 wacc[8];
        {
            const ulonglong2* bb = (const ulonglong2*)(s_wb2 + co);
#pragma unroll
            for (int c = 0; c < 4; c++) { ulonglong2 t = bb[c]; wacc[2*c] = t.x; wacc[2*c+1] = t.y; }
        }
#pragma unroll 1
        for (int m = 0; m < 64; m++) {
            const ulonglong2* w1r = (const ulonglong2*)(s_w1t + m * 32 + co);
            u64 s0 = 0ULL, s1 = 0ULL;
#pragma unroll
            for (int c = 0; c < 4; c++) {
                ulonglong2 t = w1r[c];
                s0 = fma2(u2[2*c],   t.x, s0);
                s1 = fma2(u2[2*c+1], t.y, s1);
            }
            s0 = add2(s0, s1);
            float pa, pb; unpack2(s0, pa, pb);
            float part = pa + pb;
            part += __shfl_xor_sync(0xffffffffu, part, 1);
            float hh = leaky(part + s_wb1[m]);
            const u64 h2 = pack2(hh, hh);
            const ulonglong2* w2r = (const ulonglong2*)(s_w2 + m * 32 + co);
#pragma unroll
            for (int c = 0; c < 4; c++) {
                ulonglong2 t = w2r[c];
                wacc[2*c]   = fma2(h2, t.x, wacc[2*c]);
                wacc[2*c+1] = fma2(h2, t.y, wacc[2*c+1]);
            }
        }

        float wf[16];
#pragma unroll
        for (int c = 0; c < 8; c++) unpack2(wacc[c], wf[2*c], wf[2*c+1]);
        float mx = wf[0];
#pragma unroll
        for (int c = 1; c < 16; c++) mx = fmaxf(mx, wf[c]);
        mx = fmaxf(mx, __shfl_xor_sync(0xffffffffu, mx, 1));
        float ssum = 0.f;
#pragma unroll
        for (int c = 0; c < 16; c++) { float e = __expf(wf[c] - mx); wf[c] = e; ssum += e; }
        ssum += __shfl_xor_sync(0xffffffffu, ssum, 1);
        const float inv = __frcp_rn(ssum);

        u64 e2[8];
#pragma unroll
        for (int c = 0; c < 8; c++) e2[c] = pack2(wf[2*c] * inv, wf[2*c+1] * inv);
#pragma unroll
        for (int c = 0; c < 8; c++) acc2[c] = fma2(e2[c], pos2[c], acc2[c]);

        u64 vt[8];
        mlp_half(s_mw1 + 2*48, s_mb1 + 2*16, s_mw2 + 2*512 + co, s_mb2 + 2*32 + co,
                 cx, cy, cz, vt);
#pragma unroll
        for (int c = 0; c < 8; c++) acc2[c] = fma2(e2[c], vt[c], acc2[c]);
    }

    // ================= neighbor pairs (j = 2t+1, 2t+2), shared weight loads =========
#pragma unroll 1
    for (int t = 0; t < KNB / 2; t++) {
        const float* na = other + (p * KNB + 2 * t) * 3;
        const float a0 = na[0], a1 = na[1], a2 = na[2];
        const float b0 = na[3], b1v = na[4], b2v = na[5];

        u64 pa[8], pb[8];
        mlp_half_dual(s_mw1 + 5*48, s_mb1 + 5*16, s_mw2 + 5*512 + co, s_mb2 + 5*32 + co,
                      cx - a0, cy - a1, cz - a2, cx - b0, cy - b1v, cz - b2v, pa, pb);

        u64 ua[8], ub[8];
        mlp_half_dual(s_mw1 + 3*48, s_mb1 + 3*16, s_mw2 + 3*512 + co, s_mb2 + 3*32 + co,
                      a0, a1, a2, b0, b1v, b2v, ua, ub);
#pragma unroll
        for (int c = 0; c < 8; c++) {
            ua[c] = add2(add2(q2[c], pa[c]), neg2(ua[c]));
            ub[c] = add2(add2(q2[c], pb[c]), neg2(ub[c]));
        }

        // WP dual: weight rows loaded once, used for both neighbors
        u64 wa[8], wb_[8];
        {
            const ulonglong2* bb = (const ulonglong2*)(s_wb2 + co);
#pragma unroll
            for (int c = 0; c < 4; c++) {
                ulonglong2 v = bb[c];
                wa[2*c] = v.x; wa[2*c+1] = v.y;
                wb_[2*c] = v.x; wb_[2*c+1] = v.y;
            }
        }
#pragma unroll 1
        for (int m = 0; m < 64; m++) {
            const ulonglong2* w1r = (const ulonglong2*)(s_w1t + m * 32 + co);
            u64 sa0 = 0ULL, sa1 = 0ULL, sb0 = 0ULL, sb1 = 0ULL;
#pragma unroll
            for (int c = 0; c < 4; c++) {
                ulonglong2 v = w1r[c];
                sa0 = fma2(ua[2*c],   v.x, sa0);
                sa1 = fma2(ua[2*c+1], v.y, sa1);
                sb0 = fma2(ub[2*c],   v.x, sb0);
                sb1 = fma2(ub[2*c+1], v.y, sb1);
            }
            sa0 = add2(sa0, sa1); sb0 = add2(sb0, sb1);
            float xa, ya; unpack2(sa0, xa, ya);
            float xb, yb; unpack2(sb0, xb, yb);
            float parta = xa + ya, partb = xb + yb;
            parta += __shfl_xor_sync(0xffffffffu, parta, 1);
            partb += __shfl_xor_sync(0xffffffffu, partb, 1);
            const float bm = s_wb1[m];
            const float hha = leaky(parta + bm);
            const float hhb = leaky(partb + bm);
            const u64 h2a = pack2(hha, hha);
            const u64 h2b = pack2(hhb, hhb);
            const ulonglong2* w2r = (const ulonglong2*)(s_w2 + m * 32 + co);
#pragma unroll
            for (int c = 0; c < 4; c++) {
                ulonglong2 v = w2r[c];
                wa[2*c]    = fma2(h2a, v.x, wa[2*c]);
                wa[2*c+1]  = fma2(h2a, v.y, wa[2*c+1]);
                wb_[2*c]   = fma2(h2b, v.x, wb_[2*c]);
                wb_[2*c+1] = fma2(h2b, v.y, wb_[2*c+1]);
            }
        }

        // dual softmax
        float wfa[16], wfb[16];
#pragma unroll
        for (int c = 0; c < 8; c++) { unpack2(wa[c], wfa[2*c], wfa[2*c+1]); unpack2(wb_[c], wfb[2*c], wfb[2*c+1]); }
        float mxa = wfa[0], mxb = wfb[0];
#pragma unroll
        for (int c = 1; c < 16; c++) { mxa = fmaxf(mxa, wfa[c]); mxb = fmaxf(mxb, wfb[c]); }
        mxa = fmaxf(mxa, __shfl_xor_sync(0xffffffffu, mxa, 1));
        mxb = fmaxf(mxb, __shfl_xor_sync(0xffffffffu, mxb, 1));
        float sa = 0.f, sb = 0.f;
#pragma unroll
        for (int c = 0; c < 16; c++) {
            float ea = __expf(wfa[c] - mxa); wfa[c] = ea; sa += ea;
            float eb = __expf(wfb[c] - mxb); wfb[c] = eb; sb += eb;
        }
        sa += __shfl_xor_sync(0xffffffffu, sa, 1);
        sb += __shfl_xor_sync(0xffffffffu, sb, 1);
        const float inva = __frcp_rn(sa);
        const float invb = __frcp_rn(sb);

        u64 ea2[8], eb2[8];
#pragma unroll
        for (int c = 0; c < 8; c++) {
            ea2[c] = pack2(wfa[2*c] * inva, wfa[2*c+1] * inva);
            eb2[c] = pack2(wfb[2*c] * invb, wfb[2*c+1] * invb);
        }
        // acc += e*pos (pos dies here)
#pragma unroll
        for (int c = 0; c < 8; c++) {
            acc2[c] = fma2(ea2[c], pa[c], acc2[c]);
            acc2[c] = fma2(eb2[c], pb[c], acc2[c]);
        }
        // v-MLP dual, then acc += e*v
        u64 va[8], vb2[8];
        mlp_half_dual(s_mw1 + 4*48, s_mb1 + 4*16, s_mw2 + 4*512 + co, s_mb2 + 4*32 + co,
                      a0, a1, a2, b0, b1v, b2v, va, vb2);
#pragma unroll
        for (int c = 0; c < 8; c++) {
            acc2[c] = fma2(ea2[c], va[c], acc2[c]);
            acc2[c] = fma2(eb2[c], vb2[c], acc2[c]);
        }
    }

    ulonglong2* op = (ulonglong2*)(out + p * 32 + co);
#pragma unroll
    for (int c = 0; c < 4; c++) {
        ulonglong2 v; v.x = acc2[2*c]; v.y = acc2[2*c+1];
        op[c] = v;
    }
}

extern "C" void kernel_launch(void* const* d_in, const int* in_sizes, int n_in,
                              void* d_out, int out_size)
{
    const float* center = (const float*)d_in[0];
    const float* other  = (const float*)d_in[1];
    const float* mw1    = (const float*)d_in[2];
    const float* mb1    = (const float*)d_in[3];
    const float* mw2    = (const float*)d_in[4];
    const float* mb2    = (const float*)d_in[5];
    const float* ww1    = (const float*)d_in[6];
    const float* wb1    = (const float*)d_in[7];
    const float* ww2    = (const float*)d_in[8];
    const float* wb2    = (const float*)d_in[9];
    float* out = (float*)d_out;

    const int P = in_sizes[0] / 3;
    const int block = 128;
    const int grid = (2 * P + block - 1) / block;
    pae_kernel<<<grid, block>>>(center, other, mw1, mb1, mw2, mb2,
                                ww1, wb1, ww2, wb2, out, P);
}

// round 9
// speedup vs baseline: 1.0747x; 1.0747x over previous
#include <cuda_runtime.h>

// PointAttentionEncoder1D — 4 threads/point (8 ch each), f32x2 packed,
// dual-neighbor processing: every weight LDS feeds FMAs for two neighbors.
// Register-lean so (128,4) holds 128 regs with zero spills.

typedef unsigned long long u64;
constexpr int KNB = 16;

__device__ __forceinline__ u64 pack2(float lo, float hi) {
    u64 r; asm("mov.b64 %0, {%1,%2};" : "=l"(r) : "f"(lo), "f"(hi)); return r;
}
__device__ __forceinline__ void unpack2(u64 v, float& lo, float& hi) {
    asm("mov.b64 {%0,%1}, %2;" : "=f"(lo), "=f"(hi) : "l"(v));
}
__device__ __forceinline__ u64 fma2(u64 a, u64 b, u64 c) {
    u64 d; asm("fma.rn.f32x2 %0, %1, %2, %3;" : "=l"(d) : "l"(a), "l"(b), "l"(c)); return d;
}
__device__ __forceinline__ u64 add2(u64 a, u64 b) {
    u64 d; asm("add.rn.f32x2 %0, %1, %2;" : "=l"(d) : "l"(a), "l"(b)); return d;
}
__device__ __forceinline__ u64 neg2(u64 a) { return a ^ 0x8000000080000000ULL; }
__device__ __forceinline__ float leaky(float v) { return fmaxf(v, 0.01f * v); }

// ---- single: MLP 3->16(leaky)->32, this thread's 8-channel quarter ----
__device__ __forceinline__ void mlp_q(
    const float* __restrict__ w1, const float* __restrict__ b1,
    const float* __restrict__ w2q, const float* __restrict__ b2q,
    float x0, float x1, float x2, u64* __restrict__ o)   // o[4] = 8 ch
{
    const u64 X0 = pack2(x0, x0), X1 = pack2(x1, x1), X2 = pack2(x2, x2);
    float h[16];
#pragma unroll
    for (int i = 0; i < 8; i++) {
        u64 a = *(const u64*)(b1 + 2 * i);
        a = fma2(X0, *(const u64*)(w1 + 2 * i),      a);
        a = fma2(X1, *(const u64*)(w1 + 16 + 2 * i), a);
        a = fma2(X2, *(const u64*)(w1 + 32 + 2 * i), a);
        float va, vb; unpack2(a, va, vb);
        h[2 * i] = leaky(va); h[2 * i + 1] = leaky(vb);
    }
    {
        const ulonglong2* bb = (const ulonglong2*)b2q;
        ulonglong2 t0 = bb[0], t1 = bb[1];
        o[0] = t0.x; o[1] = t0.y; o[2] = t1.x; o[3] = t1.y;
    }
#pragma unroll
    for (int i = 0; i < 16; i++) {
        const u64 h2 = pack2(h[i], h[i]);
        const ulonglong2* w2r = (const ulonglong2*)(w2q + i * 32);
        ulonglong2 t0 = w2r[0], t1 = w2r[1];
        o[0] = fma2(h2, t0.x, o[0]); o[1] = fma2(h2, t0.y, o[1]);
        o[2] = fma2(h2, t1.x, o[2]); o[3] = fma2(h2, t1.y, o[3]);
    }
}

// ---- dual: same MLP for two inputs, weight loads shared ----
__device__ __forceinline__ void mlp_q_dual(
    const float* __restrict__ w1, const float* __restrict__ b1,
    const float* __restrict__ w2q, const float* __restrict__ b2q,
    float a0, float a1, float a2, float e0, float e1, float e2,
    u64* __restrict__ oa, u64* __restrict__ ob)
{
    const u64 A0 = pack2(a0, a0), A1 = pack2(a1, a1), A2 = pack2(a2, a2);
    const u64 B0 = pack2(e0, e0), B1 = pack2(e1, e1), B2 = pack2(e2, e2);
    float ha[16], hb[16];
#pragma unroll
    for (int i = 0; i < 8; i++) {
        u64 w0  = *(const u64*)(w1 + 2 * i);
        u64 w16 = *(const u64*)(w1 + 16 + 2 * i);
        u64 w32 = *(const u64*)(w1 + 32 + 2 * i);
        u64 bb  = *(const u64*)(b1 + 2 * i);
        u64 sa = fma2(A0, w0, bb); sa = fma2(A1, w16, sa); sa = fma2(A2, w32, sa);
        u64 sb = fma2(B0, w0, bb); sb = fma2(B1, w16, sb); sb = fma2(B2, w32, sb);
        float va, vb; unpack2(sa, va, vb);
        ha[2*i] = leaky(va); ha[2*i+1] = leaky(vb);
        unpack2(sb, va, vb);
        hb[2*i] = leaky(va); hb[2*i+1] = leaky(vb);
    }
    {
        const ulonglong2* bb = (const ulonglong2*)b2q;
        ulonglong2 t0 = bb[0], t1 = bb[1];
        oa[0] = t0.x; oa[1] = t0.y; oa[2] = t1.x; oa[3] = t1.y;
        ob[0] = t0.x; ob[1] = t0.y; ob[2] = t1.x; ob[3] = t1.y;
    }
#pragma unroll
    for (int i = 0; i < 16; i++) {
        const u64 h2a = pack2(ha[i], ha[i]);
        const u64 h2b = pack2(hb[i], hb[i]);
        const ulonglong2* w2r = (const ulonglong2*)(w2q + i * 32);
        ulonglong2 t0 = w2r[0], t1 = w2r[1];
        oa[0] = fma2(h2a, t0.x, oa[0]); oa[1] = fma2(h2a, t0.y, oa[1]);
        oa[2] = fma2(h2a, t1.x, oa[2]); oa[3] = fma2(h2a, t1.y, oa[3]);
        ob[0] = fma2(h2b, t0.x, ob[0]); ob[1] = fma2(h2b, t0.y, ob[1]);
        ob[2] = fma2(h2b, t1.x, ob[2]); ob[3] = fma2(h2b, t1.y, ob[3]);
    }
}

// 4-lane sum (lanes grouped as p*4+quarter, aligned)
__device__ __forceinline__ float qsum(float v) {
    v += __shfl_xor_sync(0xffffffffu, v, 1);
    v += __shfl_xor_sync(0xffffffffu, v, 2);
    return v;
}
__device__ __forceinline__ float qmax(float v) {
    v = fmaxf(v, __shfl_xor_sync(0xffffffffu, v, 1));
    v = fmaxf(v, __shfl_xor_sync(0xffffffffu, v, 2));
    return v;
}

__global__ void __launch_bounds__(128, 4)
pae_kernel(const float* __restrict__ center, const float* __restrict__ other,
           const float* __restrict__ mw1, const float* __restrict__ mb1,
           const float* __restrict__ mw2, const float* __restrict__ mb2,
           const float* __restrict__ ww1, const float* __restrict__ wb1,
           const float* __restrict__ ww2, const float* __restrict__ wb2,
           float* __restrict__ out, int P)
{
    __shared__ __align__(16) float s_mw1[6 * 48];
    __shared__ __align__(16) float s_mb1[6 * 16];
    __shared__ __align__(16) float s_mw2[6 * 512];
    __shared__ __align__(16) float s_mb2[6 * 32];
    __shared__ __align__(16) float s_w1t[64 * 32];   // wp_w1 transposed: [m][c]
    __shared__ __align__(16) float s_wb1[64];
    __shared__ __align__(16) float s_w2[64 * 32];    // wp_w2: [m][c]
    __shared__ __align__(16) float s_wb2[32];

    const int tid = threadIdx.x;
    const int nt  = blockDim.x;
    for (int i = tid; i < 6 * 48;  i += nt) s_mw1[i] = mw1[i];
    for (int i = tid; i < 6 * 16;  i += nt) s_mb1[i] = mb1[i];
    for (int i = tid; i < 6 * 512; i += nt) s_mw2[i] = mw2[i];
    for (int i = tid; i < 6 * 32;  i += nt) s_mb2[i] = mb2[i];
    for (int i = tid; i < 32 * 64; i += nt) {
        int c = i >> 6, m = i & 63;
        s_w1t[m * 32 + c] = ww1[i];
    }
    for (int i = tid; i < 64;      i += nt) s_wb1[i] = wb1[i];
    for (int i = tid; i < 64 * 32; i += nt) s_w2[i] = ww2[i];
    for (int i = tid; i < 32;      i += nt) s_wb2[i] = wb2[i];
    __syncthreads();

    const int g = blockIdx.x * nt + tid;
    if (g >= 4 * P) return;
    const int p  = g >> 2;
    const int co = 8 * (g & 3);                      // channel offset (quarter)

    const float cx = center[p * 3 + 0];
    const float cy = center[p * 3 + 1];
    const float cz = center[p * 3 + 2];

    u64 q2[4];
    mlp_q(s_mw1, s_mb1, s_mw2 + co, s_mb2 + co, cx, cy, cz, q2);

    u64 acc2[4];
#pragma unroll
    for (int c = 0; c < 4; c++) acc2[c] = 0ULL;

    // ================= j = 0 : center-as-neighbor (single path) =================
    {
        u64 pos2[4];
        mlp_q(s_mw1 + 5*48, s_mb1 + 5*16, s_mw2 + 5*512 + co, s_mb2 + 5*32 + co,
              0.f, 0.f, 0.f, pos2);
        u64 u2[4];
        mlp_q(s_mw1 + 1*48, s_mb1 + 1*16, s_mw2 + 1*512 + co, s_mb2 + 1*32 + co,
              cx, cy, cz, u2);
#pragma unroll
        for (int c = 0; c < 4; c++)
            u2[c] = add2(add2(q2[c], pos2[c]), neg2(u2[c]));

        u64 wacc[4];
        {
            const ulonglong2* bb = (const ulonglong2*)(s_wb2 + co);
            ulonglong2 t0 = bb[0], t1 = bb[1];
            wacc[0] = t0.x; wacc[1] = t0.y; wacc[2] = t1.x; wacc[3] = t1.y;
        }
#pragma unroll 2
        for (int m = 0; m < 64; m++) {
            const ulonglong2* w1r = (const ulonglong2*)(s_w1t + m * 32 + co);
            ulonglong2 t0 = w1r[0], t1 = w1r[1];
            u64 s0 = fma2(u2[0], t0.x, 0ULL);
            u64 s1 = fma2(u2[1], t0.y, 0ULL);
            s0 = fma2(u2[2], t1.x, s0);
            s1 = fma2(u2[3], t1.y, s1);
            s0 = add2(s0, s1);
            float pa, pb; unpack2(s0, pa, pb);
            float hh = leaky(qsum(pa + pb) + s_wb1[m]);
            const u64 h2 = pack2(hh, hh);
            const ulonglong2* w2r = (const ulonglong2*)(s_w2 + m * 32 + co);
            ulonglong2 v0 = w2r[0], v1 = w2r[1];
            wacc[0] = fma2(h2, v0.x, wacc[0]); wacc[1] = fma2(h2, v0.y, wacc[1]);
            wacc[2] = fma2(h2, v1.x, wacc[2]); wacc[3] = fma2(h2, v1.y, wacc[3]);
        }

        float wf[8];
#pragma unroll
        for (int c = 0; c < 4; c++) unpack2(wacc[c], wf[2*c], wf[2*c+1]);
        float mx = wf[0];
#pragma unroll
        for (int c = 1; c < 8; c++) mx = fmaxf(mx, wf[c]);
        mx = qmax(mx);
        float ssum = 0.f;
#pragma unroll
        for (int c = 0; c < 8; c++) { float e = __expf(wf[c] - mx); wf[c] = e; ssum += e; }
        ssum = qsum(ssum);
        const float inv = __frcp_rn(ssum);

        u64 e2[4];
#pragma unroll
        for (int c = 0; c < 4; c++) e2[c] = pack2(wf[2*c] * inv, wf[2*c+1] * inv);
#pragma unroll
        for (int c = 0; c < 4; c++) acc2[c] = fma2(e2[c], pos2[c], acc2[c]);

        u64 vt[4];
        mlp_q(s_mw1 + 2*48, s_mb1 + 2*16, s_mw2 + 2*512 + co, s_mb2 + 2*32 + co,
              cx, cy, cz, vt);
#pragma unroll
        for (int c = 0; c < 4; c++) acc2[c] = fma2(e2[c], vt[c], acc2[c]);
    }

    // ================= neighbor pairs, weight loads shared across the pair ======
#pragma unroll 1
    for (int t = 0; t < KNB / 2; t++) {
        const float* na = other + (p * KNB + 2 * t) * 3;
        const float a0 = na[0], a1 = na[1], a2 = na[2];
        const float b0 = na[3], b1v = na[4], b2v = na[5];

        u64 pa[4], pb[4];
        mlp_q_dual(s_mw1 + 5*48, s_mb1 + 5*16, s_mw2 + 5*512 + co, s_mb2 + 5*32 + co,
                   cx - a0, cy - a1, cz - a2, cx - b0, cy - b1v, cz - b2v, pa, pb);

        u64 ua[4], ub[4];
        mlp_q_dual(s_mw1 + 3*48, s_mb1 + 3*16, s_mw2 + 3*512 + co, s_mb2 + 3*32 + co,
                   a0, a1, a2, b0, b1v, b2v, ua, ub);
#pragma unroll
        for (int c = 0; c < 4; c++) {
            ua[c] = add2(add2(q2[c], pa[c]), neg2(ua[c]));
            ub[c] = add2(add2(q2[c], pb[c]), neg2(ub[c]));
        }

        // WP dual: weight rows loaded once per pair
        u64 wa[4], wb_[4];
        {
            const ulonglong2* bb = (const ulonglong2*)(s_wb2 + co);
            ulonglong2 t0 = bb[0], t1 = bb[1];
            wa[0] = t0.x;  wa[1] = t0.y;  wa[2] = t1.x;  wa[3] = t1.y;
            wb_[0] = t0.x; wb_[1] = t0.y; wb_[2] = t1.x; wb_[3] = t1.y;
        }
#pragma unroll 2
        for (int m = 0; m < 64; m++) {
            const ulonglong2* w1r = (const ulonglong2*)(s_w1t + m * 32 + co);
            ulonglong2 t0 = w1r[0], t1 = w1r[1];
            u64 sa0 = fma2(ua[0], t0.x, 0ULL);
            u64 sa1 = fma2(ua[1], t0.y, 0ULL);
            sa0 = fma2(ua[2], t1.x, sa0);
            sa1 = fma2(ua[3], t1.y, sa1);
            u64 sb0 = fma2(ub[0], t0.x, 0ULL);
            u64 sb1 = fma2(ub[1], t0.y, 0ULL);
            sb0 = fma2(ub[2], t1.x, sb0);
            sb1 = fma2(ub[3], t1.y, sb1);
            sa0 = add2(sa0, sa1); sb0 = add2(sb0, sb1);
            float xa, ya; unpack2(sa0, xa, ya);
            float xb, yb; unpack2(sb0, xb, yb);
            const float bm = s_wb1[m];
            const float hha = leaky(qsum(xa + ya) + bm);
            const float hhb = leaky(qsum(xb + yb) + bm);
            const u64 h2a = pack2(hha, hha);
            const u64 h2b = pack2(hhb, hhb);
            const ulonglong2* w2r = (const ulonglong2*)(s_w2 + m * 32 + co);
            ulonglong2 v0 = w2r[0], v1 = w2r[1];
            wa[0]  = fma2(h2a, v0.x, wa[0]);  wa[1]  = fma2(h2a, v0.y, wa[1]);
            wa[2]  = fma2(h2a, v1.x, wa[2]);  wa[3]  = fma2(h2a, v1.y, wa[3]);
            wb_[0] = fma2(h2b, v0.x, wb_[0]); wb_[1] = fma2(h2b, v0.y, wb_[1]);
            wb_[2] = fma2(h2b, v1.x, wb_[2]); wb_[3] = fma2(h2b, v1.y, wb_[3]);
        }

        // dual softmax over 32 channels (8 local + 4-lane reduce)
        float wfa[8], wfb[8];
#pragma unroll
        for (int c = 0; c < 4; c++) { unpack2(wa[c], wfa[2*c], wfa[2*c+1]); unpack2(wb_[c], wfb[2*c], wfb[2*c+1]); }
        float mxa = wfa[0], mxb = wfb[0];
#pragma unroll
        for (int c = 1; c < 8; c++) { mxa = fmaxf(mxa, wfa[c]); mxb = fmaxf(mxb, wfb[c]); }
        mxa = qmax(mxa); mxb = qmax(mxb);
        float sa = 0.f, sb = 0.f;
#pragma unroll
        for (int c = 0; c < 8; c++) {
            float ea = __expf(wfa[c] - mxa); wfa[c] = ea; sa += ea;
            float eb = __expf(wfb[c] - mxb); wfb[c] = eb; sb += eb;
        }
        sa = qsum(sa); sb = qsum(sb);
        const float inva = __frcp_rn(sa);
        const float invb = __frcp_rn(sb);

        u64 ea2[4], eb2[4];
#pragma unroll
        for (int c = 0; c < 4; c++) {
            ea2[c] = pack2(wfa[2*c] * inva, wfa[2*c+1] * inva);
            eb2[c] = pack2(wfb[2*c] * invb, wfb[2*c+1] * invb);
        }
#pragma unroll
        for (int c = 0; c < 4; c++) {
            acc2[c] = fma2(ea2[c], pa[c], acc2[c]);
            acc2[c] = fma2(eb2[c], pb[c], acc2[c]);
        }
        u64 va[4], vb2[4];
        mlp_q_dual(s_mw1 + 4*48, s_mb1 + 4*16, s_mw2 + 4*512 + co, s_mb2 + 4*32 + co,
                   a0, a1, a2, b0, b1v, b2v, va, vb2);
#pragma unroll
        for (int c = 0; c < 4; c++) {
            acc2[c] = fma2(ea2[c], va[c], acc2[c]);
            acc2[c] = fma2(eb2[c], vb2[c], acc2[c]);
        }
    }

    ulonglong2* op = (ulonglong2*)(out + p * 32 + co);
    ulonglong2 o0; o0.x = acc2[0]; o0.y = acc2[1];
    ulonglong2 o1; o1.x = acc2[2]; o1.y = acc2[3];
    op[0] = o0; op[1] = o1;
}

extern "C" void kernel_launch(void* const* d_in, const int* in_sizes, int n_in,
                              void* d_out, int out_size)
{
    const float* center = (const float*)d_in[0];
    const float* other  = (const float*)d_in[1];
    const float* mw1    = (const float*)d_in[2];
    const float* mb1    = (const float*)d_in[3];
    const float* mw2    = (const float*)d_in[4];
    const float* mb2    = (const float*)d_in[5];
    const float* ww1    = (const float*)d_in[6];
    const float* wb1    = (const float*)d_in[7];
    const float* ww2    = (const float*)d_in[8];
    const float* wb2    = (const float*)d_in[9];
    float* out = (float*)d_out;

    const int P = in_sizes[0] / 3;
    const int block = 128;
    const int grid = (4 * P + block - 1) / block;
    pae_kernel<<<grid, block>>>(center, other, mw1, mb1, mw2, mb2,
                                ww1, wb1, ww2, wb2, out, P);
}

// round 12
// speedup vs baseline: 2.1901x; 2.0378x over previous
#include <cuda_runtime.h>

// PointAttentionEncoder1D — 2 threads/point (16 ch each), f32x2 packed.
// R6 structure (proven no-spill) + occupancy 4 blocks/SM + coord prefetch.

typedef unsigned long long u64;
constexpr int KNB = 16;

__device__ __forceinline__ u64 pack2(float lo, float hi) {
    u64 r; asm("mov.b64 %0, {%1,%2};" : "=l"(r) : "f"(lo), "f"(hi)); return r;
}
__device__ __forceinline__ void unpack2(u64 v, float& lo, float& hi) {
    asm("mov.b64 {%0,%1}, %2;" : "=f"(lo), "=f"(hi) : "l"(v));
}
__device__ __forceinline__ u64 fma2(u64 a, u64 b, u64 c) {
    u64 d; asm("fma.rn.f32x2 %0, %1, %2, %3;" : "=l"(d) : "l"(a), "l"(b), "l"(c)); return d;
}
__device__ __forceinline__ u64 add2(u64 a, u64 b) {
    u64 d; asm("add.rn.f32x2 %0, %1, %2;" : "=l"(d) : "l"(a), "l"(b)); return d;
}
__device__ __forceinline__ u64 neg2(u64 a) { return a ^ 0x8000000080000000ULL; }
__device__ __forceinline__ float leaky(float v) { return fmaxf(v, 0.01f * v); }

// MLP 3 -> 16 (leaky) -> 32, this thread's 16-channel half.
__device__ __forceinline__ void mlp_half(
    const float* __restrict__ w1, const float* __restrict__ b1,
    const float* __restrict__ w2h, const float* __restrict__ b2h,
    float x0, float x1, float x2, u64* __restrict__ o)
{
    const u64 X0 = pack2(x0, x0), X1 = pack2(x1, x1), X2 = pack2(x2, x2);
    float h[16];
#pragma unroll
    for (int i = 0; i < 8; i++) {
        u64 a = *(const u64*)(b1 + 2 * i);
        a = fma2(X0, *(const u64*)(w1 + 2 * i),      a);
        a = fma2(X1, *(const u64*)(w1 + 16 + 2 * i), a);
        a = fma2(X2, *(const u64*)(w1 + 32 + 2 * i), a);
        float va, vb; unpack2(a, va, vb);
        h[2 * i] = leaky(va); h[2 * i + 1] = leaky(vb);
    }
    const ulonglong2* bb = (const ulonglong2*)b2h;
#pragma unroll
    for (int c = 0; c < 4; c++) { ulonglong2 t = bb[c]; o[2*c] = t.x; o[2*c+1] = t.y; }
#pragma unroll
    for (int i = 0; i < 16; i++) {
        const u64 h2 = pack2(h[i], h[i]);
        const ulonglong2* w2r = (const ulonglong2*)(w2h + i * 32);
#pragma unroll
        for (int c = 0; c < 4; c++) {
            ulonglong2 t = w2r[c];
            o[2*c]   = fma2(h2, t.x, o[2*c]);
            o[2*c+1] = fma2(h2, t.y, o[2*c+1]);
        }
    }
}

__global__ void __launch_bounds__(128, 4)
pae_kernel(const float* __restrict__ center,   // [P,1,3]
           const float* __restrict__ other,    // [P,K,3]
           const float* __restrict__ mw1,      // [6,3,16]
           const float* __restrict__ mb1,      // [6,16]
           const float* __restrict__ mw2,      // [6,16,32]
           const float* __restrict__ mb2,      // [6,32]
           const float* __restrict__ ww1,      // [32,64]
           const float* __restrict__ wb1,      // [64]
           const float* __restrict__ ww2,      // [64,32]
           const float* __restrict__ wb2,      // [32]
           float* __restrict__ out,            // [P,32]
           int P)
{
    __shared__ __align__(16) float s_mw1[6 * 48];
    __shared__ __align__(16) float s_mb1[6 * 16];
    __shared__ __align__(16) float s_mw2[6 * 512];
    __shared__ __align__(16) float s_mb2[6 * 32];
    __shared__ __align__(16) float s_w1t[64 * 32];   // wp_w1 transposed: [m][c]
    __shared__ __align__(16) float s_wb1[64];
    __shared__ __align__(16) float s_w2[64 * 32];    // wp_w2: [m][c]
    __shared__ __align__(16) float s_wb2[32];

    const int tid = threadIdx.x;
    const int nt  = blockDim.x;
    for (int i = tid; i < 6 * 48;  i += nt) s_mw1[i] = mw1[i];
    for (int i = tid; i < 6 * 16;  i += nt) s_mb1[i] = mb1[i];
    for (int i = tid; i < 6 * 512; i += nt) s_mw2[i] = mw2[i];
    for (int i = tid; i < 6 * 32;  i += nt) s_mb2[i] = mb2[i];
    for (int i = tid; i < 32 * 64; i += nt) {
        int c = i >> 6, m = i & 63;
        s_w1t[m * 32 + c] = ww1[i];
    }
    for (int i = tid; i < 64;      i += nt) s_wb1[i] = wb1[i];
    for (int i = tid; i < 64 * 32; i += nt) s_w2[i] = ww2[i];
    for (int i = tid; i < 32;      i += nt) s_wb2[i] = wb2[i];
    __syncthreads();

    const int g = blockIdx.x * nt + tid;
    if (g >= 2 * P) return;
    const int p    = g >> 1;
    const int half = g & 1;
    const int co   = 16 * half;

    const float cx = center[p * 3 + 0];
    const float cy = center[p * 3 + 1];
    const float cz = center[p * 3 + 2];

    u64 q2[8];
    mlp_half(s_mw1, s_mb1, s_mw2 + co, s_mb2 + co, cx, cy, cz, q2);

    u64 acc2[8];
#pragma unroll
    for (int c = 0; c < 8; c++) acc2[c] = 0ULL;

    // prefetch first neighbor's coords
    const float* onb = other + p * KNB * 3;
    float n0 = onb[0], n1 = onb[1], n2 = onb[2];

#pragma unroll 1
    for (int j = 0; j <= KNB; j++) {
        float x0, x1, x2;
        int kb, vb;
        if (j == 0) { x0 = cx; x1 = cy; x2 = cz; kb = 1; vb = 2; }
        else        { x0 = n0; x1 = n1; x2 = n2; kb = 3; vb = 4; }
        // prefetch next neighbor early (hides LDG latency behind the MLPs)
        if (j < KNB) {
            const float* nn = onb + j * 3;
            n0 = nn[0]; n1 = nn[1]; n2 = nn[2];
        }

        // pos = MLP5(center - x)
        u64 pos2[8];
        mlp_half(s_mw1 + 5*48, s_mb1 + 5*16, s_mw2 + 5*512 + co, s_mb2 + 5*32 + co,
                 cx - x0, cy - x1, cz - x2, pos2);

        // u = q - k + pos
        u64 u2[8];
        mlp_half(s_mw1 + kb*48, s_mb1 + kb*16, s_mw2 + kb*512 + co, s_mb2 + kb*32 + co,
                 x0, x1, x2, u2);
#pragma unroll
        for (int c = 0; c < 8; c++)
            u2[c] = add2(add2(q2[c], pos2[c]), neg2(u2[c]));

        // weight_process 32 -> 64 (leaky) -> 32; 16-ch partial dots + pair shfl
        u64 wacc[8];
        {
            const ulonglong2* bb = (const ulonglong2*)(s_wb2 + co);
#pragma unroll
            for (int c = 0; c < 4; c++) { ulonglong2 t = bb[c]; wacc[2*c] = t.x; wacc[2*c+1] = t.y; }
        }
#pragma unroll 2
        for (int m = 0; m < 64; m++) {
            const ulonglong2* w1r = (const ulonglong2*)(s_w1t + m * 32 + co);
            u64 s0 = 0ULL, s1 = 0ULL;
#pragma unroll
            for (int c = 0; c < 4; c++) {
                ulonglong2 t = w1r[c];
                s0 = fma2(u2[2*c],   t.x, s0);
                s1 = fma2(u2[2*c+1], t.y, s1);
            }
            s0 = add2(s0, s1);
            float pa, pb; unpack2(s0, pa, pb);
            float part = pa + pb;
            part += __shfl_xor_sync(0xffffffffu, part, 1);
            float hh = leaky(part + s_wb1[m]);
            const u64 h2 = pack2(hh, hh);
            const ulonglong2* w2r = (const ulonglong2*)(s_w2 + m * 32 + co);
#pragma unroll
            for (int c = 0; c < 4; c++) {
                ulonglong2 t = w2r[c];
                wacc[2*c]   = fma2(h2, t.x, wacc[2*c]);
                wacc[2*c+1] = fma2(h2, t.y, wacc[2*c+1]);
            }
        }

        // softmax over all 32 channels (16 local + pair shfl for max/sum)
        float wf[16];
#pragma unroll
        for (int c = 0; c < 8; c++) unpack2(wacc[c], wf[2*c], wf[2*c+1]);
        float mx = wf[0];
#pragma unroll
        for (int c = 1; c < 16; c++) mx = fmaxf(mx, wf[c]);
        mx = fmaxf(mx, __shfl_xor_sync(0xffffffffu, mx, 1));
        float ssum = 0.f;
#pragma unroll
        for (int c = 0; c < 16; c++) { float e = __expf(wf[c] - mx); wf[c] = e; ssum += e; }
        ssum += __shfl_xor_sync(0xffffffffu, ssum, 1);
        const float inv = __frcp_rn(ssum);

        u64 e2[8];
#pragma unroll
        for (int c = 0; c < 8; c++)
            e2[c] = pack2(wf[2*c] * inv, wf[2*c+1] * inv);

        // acc += e * pos   (pos dead afterwards)
#pragma unroll
        for (int c = 0; c < 8; c++) acc2[c] = fma2(e2[c], pos2[c], acc2[c]);

        // v-MLP into temp, then acc += e * v
        u64 vt[8];
        mlp_half(s_mw1 + vb*48, s_mb1 + vb*16, s_mw2 + vb*512 + co, s_mb2 + vb*32 + co,
                 x0, x1, x2, vt);
#pragma unroll
        for (int c = 0; c < 8; c++) acc2[c] = fma2(e2[c], vt[c], acc2[c]);
    }

    // store this half's 16 floats (4x STG.128), coalesced across the pair
    ulonglong2* op = (ulonglong2*)(out + p * 32 + co);
#pragma unroll
    for (int c = 0; c < 4; c++) {
        ulonglong2 t; t.x = acc2[2*c]; t.y = acc2[2*c+1];
        op[c] = t;
    }
}

extern "C" void kernel_launch(void* const* d_in, const int* in_sizes, int n_in,
                              void* d_out, int out_size)
{
    const float* center = (const float*)d_in[0];
    const float* other  = (const float*)d_in[1];
    const float* mw1    = (const float*)d_in[2];
    const float* mb1    = (const float*)d_in[3];
    const float* mw2    = (const float*)d_in[4];
    const float* mb2    = (const float*)d_in[5];
    const float* ww1    = (const float*)d_in[6];
    const float* wb1    = (const float*)d_in[7];
    const float* ww2    = (const float*)d_in[8];
    const float* wb2    = (const float*)d_in[9];
    float* out = (float*)d_out;

    const int P = in_sizes[0] / 3;
    const int block = 128;
    const int grid = (2 * P + block - 1) / block;
    pae_kernel<<<grid, block>>>(center, other, mw1, mb1, mw2, mb2,
                                ww1, wb1, ww2, wb2, out, P);
}